// round 1
// baseline (speedup 1.0000x reference)
#include <cuda_runtime.h>
#include <math.h>

#define NCARDS 10000
#define BATCH  16384
#define DECKL  8

// ---------------- scratch (static device globals; no allocation) ----------------
__device__ float g_emb [NCARDS * 256];      // [amp(128) | ph(128)] per card
__device__ float g_P   [NCARDS * 1536];     // per-card projections: [q_my k_my v_my q_op k_op v_op]
__device__ float g_mean[BATCH * 512];       // [mean_attn_my(256) | mean_attn_op(256)] pre-out-proj
__device__ float g_feat[BATCH * 512];       // after out projections
__device__ float g_h1  [BATCH * 256];       // after w1 (LN applied in place)
__device__ float g_w2t [256 * 64];          // w2 transposed (k-major)

// ---------------- K1: card embeddings ----------------
__global__ void emb_kernel(const float* __restrict__ xr, const float* __restrict__ xi) {
    int idx = blockIdx.x * 256 + threadIdx.x;
    if (idx >= NCARDS * 128) return;
    int c = idx >> 7, d = idx & 127;
    float a = xr[idx], b = xi[idx];
    g_emb[c * 256 + d]       = sqrtf(a * a + b * b + 1e-8f);
    g_emb[c * 256 + 128 + d] = atan2f(b, a);
}

// ---------------- generic fp32 GEMM: C[M,N] = A[M,K] * B[N,K]^T + bias[N] ----------------
// 128x128 tile, BK=8, 256 threads, 8x8 per thread
__global__ void sgemm_tn(const float* __restrict__ A, const float* __restrict__ B,
                         const float* __restrict__ bias, float* __restrict__ C,
                         int M, int N, int K, int lda, int ldb, int ldc) {
    __shared__ float sA[8][128];
    __shared__ float sB[8][128];
    int tid = threadIdx.x;
    int ty = tid >> 4, tx = tid & 15;
    int bm = blockIdx.y * 128, bn = blockIdx.x * 128;
    int lr = tid >> 1, seg = tid & 1;

    float acc[8][8];
#pragma unroll
    for (int i = 0; i < 8; i++)
#pragma unroll
        for (int j = 0; j < 8; j++) acc[i][j] = 0.f;

    for (int k0 = 0; k0 < K; k0 += 8) {
        float4 va = make_float4(0.f, 0.f, 0.f, 0.f);
        float4 vb = make_float4(0.f, 0.f, 0.f, 0.f);
        int ar = bm + lr;
        if (ar < M) va = *(const float4*)&A[(size_t)ar * lda + k0 + seg * 4];
        int br = bn + lr;
        if (br < N) vb = *(const float4*)&B[(size_t)br * ldb + k0 + seg * 4];
        __syncthreads();   // previous iteration's compute done
        sA[seg * 4 + 0][lr] = va.x; sA[seg * 4 + 1][lr] = va.y;
        sA[seg * 4 + 2][lr] = va.z; sA[seg * 4 + 3][lr] = va.w;
        sB[seg * 4 + 0][lr] = vb.x; sB[seg * 4 + 1][lr] = vb.y;
        sB[seg * 4 + 2][lr] = vb.z; sB[seg * 4 + 3][lr] = vb.w;
        __syncthreads();
#pragma unroll
        for (int k = 0; k < 8; k++) {
            float4 a0 = *(const float4*)&sA[k][ty * 8];
            float4 a1 = *(const float4*)&sA[k][ty * 8 + 4];
            float4 b0 = *(const float4*)&sB[k][tx * 8];
            float4 b1 = *(const float4*)&sB[k][tx * 8 + 4];
            float av[8] = {a0.x, a0.y, a0.z, a0.w, a1.x, a1.y, a1.z, a1.w};
            float bv[8] = {b0.x, b0.y, b0.z, b0.w, b1.x, b1.y, b1.z, b1.w};
#pragma unroll
            for (int i = 0; i < 8; i++)
#pragma unroll
                for (int j = 0; j < 8; j++) acc[i][j] += av[i] * bv[j];
        }
    }
#pragma unroll
    for (int i = 0; i < 8; i++) {
        int row = bm + ty * 8 + i;
        if (row >= M) continue;
#pragma unroll
        for (int j = 0; j < 8; j++) {
            int col = bn + tx * 8 + j;
            if (col < N) C[(size_t)row * ldc + col] = acc[i][j] + bias[col];
        }
    }
}

// ---------------- K3: per-batch dual cross-attention, mean-collapsed ----------------
// side 0 (attn_my): Q=q_my[my], K=k_my[op], V=v_my[op], bias[i][j]
// side 1 (attn_op): Q=q_op[op], K=k_op[my], V=v_op[my], bias[j][i]
// mean over queries commutes: out_mean[d] = sum_j ( (1/8) sum_i p[h,i,j] ) * V[j][d]
__global__ void attn_kernel(const int* __restrict__ my_decks, const int* __restrict__ op_decks,
                            const int* __restrict__ adj, const float* __restrict__ P,
                            float* __restrict__ meanout) {
    __shared__ int   sMy[8], sOp[8];
    __shared__ float sMat[4][8][256];   // 0:Q_A 1:Q_B 2:K_A 3:K_B   (32 KB)
    __shared__ float sBias[8][8];
    __shared__ float sS[2][4][8][8];
    __shared__ float sW[2][4][8];

    int b = blockIdx.x, t = threadIdx.x;
    if (t < 8)        sMy[t]     = my_decks[b * 8 + t];
    else if (t < 16)  sOp[t - 8] = op_decks[b * 8 + (t - 8)];
    __syncthreads();

    if (t < 64) {
        int i = t >> 3, j = t & 7;
        sBias[i][j] = (adj[(size_t)sMy[i] * NCARDS + sOp[j]] > 0) ? 0.f : -10000.f;
    }

    // gather Q/K rows (4 mats x 8 rows x 256 floats = 2048 float4)
    const int offs[4] = {0, 768, 256, 1024};
#pragma unroll
    for (int it = 0; it < 8; it++) {
        int idx  = t + it * 256;          // 0..2047
        int row  = idx >> 6;              // 0..31
        int c4   = idx & 63;
        int mat  = row >> 3, slot = row & 7;
        int card = (mat == 0 || mat == 3) ? sMy[slot] : sOp[slot];
        float4 v = *(const float4*)&P[(size_t)card * 1536 + offs[mat] + c4 * 4];
        ((float4*)&sMat[mat][slot][0])[c4] = v;
    }
    __syncthreads();

    // scores: 512 dot-products of length 64; 2 per thread
#pragma unroll
    for (int u = 0; u < 2; u++) {
        int e = t * 2 + u;
        int s = e >> 8, h = (e >> 6) & 3, a = (e >> 3) & 7, bb = e & 7;
        const float* q  = &sMat[s][a][h * 64];
        const float* kk = &sMat[2 + s][bb][h * 64];
        float dot = 0.f;
#pragma unroll
        for (int d = 0; d < 64; d += 4) {
            float4 qv = *(const float4*)&q[d];
            float4 kv = *(const float4*)&kk[d];
            dot += qv.x * kv.x + qv.y * kv.y + qv.z * kv.z + qv.w * kv.w;
        }
        float bi = (s == 0) ? sBias[a][bb] : sBias[bb][a];
        sS[s][h][a][bb] = dot * 0.125f + bi;
    }
    __syncthreads();

    // softmax over keys (rows of 8)
    if (t < 64) {
        int s = t >> 5, h = (t >> 3) & 3, a = t & 7;
        float* row = &sS[s][h][a][0];
        float m = row[0];
#pragma unroll
        for (int j = 1; j < 8; j++) m = fmaxf(m, row[j]);
        float p[8], sum = 0.f;
#pragma unroll
        for (int j = 0; j < 8; j++) { p[j] = expf(row[j] - m); sum += p[j]; }
        float inv = 1.f / sum;
#pragma unroll
        for (int j = 0; j < 8; j++) row[j] = p[j] * inv;
    }
    __syncthreads();

    // mean-collapsed weights: w[s][h][j] = (1/8) * sum_a p[s][h][a][j]
    if (t < 64) {
        int s = t >> 5, h = (t >> 3) & 3, bb = t & 7;
        float w = 0.f;
#pragma unroll
        for (int a = 0; a < 8; a++) w += sS[s][h][a][bb];
        sW[s][h][bb] = w * 0.125f;
    }
    __syncthreads();

    // output: each thread handles one side and 2 consecutive dims; V read from L2
    {
        int s  = t >> 7;
        int d0 = (t & 127) * 2;
        int h  = d0 >> 6;
        int off = (s == 0) ? 512 : 1280;
        float w[8];
#pragma unroll
        for (int j = 0; j < 8; j++) w[j] = sW[s][h][j];
        float acc0 = 0.f, acc1 = 0.f;
#pragma unroll
        for (int j = 0; j < 8; j++) {
            int card = (s == 0) ? sOp[j] : sMy[j];
            float2 v = *(const float2*)&P[(size_t)card * 1536 + off + d0];
            acc0 += w[j] * v.x; acc1 += w[j] * v.y;
        }
        *(float2*)&meanout[(size_t)b * 512 + s * 256 + d0] = make_float2(acc0, acc1);
    }
}

// ---------------- K6: LayerNorm + ReLU, in place, one warp per row of 256 ----------------
__global__ void ln_relu_kernel(float* __restrict__ h, const float* __restrict__ g,
                               const float* __restrict__ be) {
    int w = threadIdx.x >> 5, lane = threadIdx.x & 31;
    int row = blockIdx.x * 8 + w;
    float* rp = h + (size_t)row * 256;
    float4 v0 = *(float4*)&rp[lane * 8];
    float4 v1 = *(float4*)&rp[lane * 8 + 4];
    float vals[8] = {v0.x, v0.y, v0.z, v0.w, v1.x, v1.y, v1.z, v1.w};
    float s = 0.f, sq = 0.f;
#pragma unroll
    for (int q = 0; q < 8; q++) { s += vals[q]; sq += vals[q] * vals[q]; }
#pragma unroll
    for (int o = 16; o; o >>= 1) {
        s  += __shfl_xor_sync(0xffffffffu, s,  o);
        sq += __shfl_xor_sync(0xffffffffu, sq, o);
    }
    float mu   = s * (1.f / 256.f);
    float var  = sq * (1.f / 256.f) - mu * mu;
    float rstd = rsqrtf(var + 1e-5f);
#pragma unroll
    for (int q = 0; q < 8; q++) {
        int idx = lane * 8 + q;
        vals[q] = fmaxf(0.f, (vals[q] - mu) * rstd * g[idx] + be[idx]);
    }
    *(float4*)&rp[lane * 8]     = make_float4(vals[0], vals[1], vals[2], vals[3]);
    *(float4*)&rp[lane * 8 + 4] = make_float4(vals[4], vals[5], vals[6], vals[7]);
}

// ---------------- w2 transpose (k-major for coalesced head reads) ----------------
__global__ void w2t_kernel(const float* __restrict__ w2) {
    int idx = blockIdx.x * 256 + threadIdx.x;   // 64*256 = 16384
    int n = idx >> 8, k = idx & 255;
    g_w2t[k * 64 + n] = w2[idx];
}

// ---------------- K7/K8: fc2 + relu + fc3, 16 rows per block ----------------
__global__ void head_kernel(const float* __restrict__ h, const float* __restrict__ w2t,
                            const float* __restrict__ b2, const float* __restrict__ w3,
                            const float* __restrict__ b3, float* __restrict__ out) {
    __shared__ float sH[4][256];
    __shared__ float sPart[4][2];
    int t = threadIdx.x;
    int rsub = t >> 6, n = t & 63, lane = t & 31;
    float b2n = b2[n], w3n = w3[n], b3v = b3[0];

    for (int it = 0; it < 4; it++) {
        __syncthreads();   // protect previous iteration's sH/sPart readers
#pragma unroll
        for (int q = 0; q < 4; q++) {
            int fi = t + q * 256;               // 0..1023
            int rr = fi >> 8, cc = fi & 255;
            sH[rr][cc] = h[(size_t)(blockIdx.x * 16 + it * 4 + rr) * 256 + cc];
        }
        __syncthreads();
        float acc = 0.f;
#pragma unroll 8
        for (int k = 0; k < 256; k++) acc += sH[rsub][k] * w2t[k * 64 + n];
        float p = fmaxf(acc + b2n, 0.f) * w3n;
#pragma unroll
        for (int o = 16; o; o >>= 1) p += __shfl_xor_sync(0xffffffffu, p, o);
        if (lane == 0) sPart[rsub][(t >> 5) & 1] = p;
        __syncthreads();
        if (t < 4) out[blockIdx.x * 16 + it * 4 + t] = sPart[t][0] + sPart[t][1] + b3v;
    }
}

// ---------------- launch ----------------
extern "C" void kernel_launch(void* const* d_in, const int* in_sizes, int n_in,
                              void* d_out, int out_size) {
    (void)in_sizes; (void)n_in; (void)out_size;
    const float* x_real   = (const float*)d_in[0];
    const float* x_imag   = (const float*)d_in[1];
    const int*   my_decks = (const int*)  d_in[2];
    const int*   op_decks = (const int*)  d_in[3];
    const int*   adj      = (const int*)  d_in[4];
    const float* in_w_my  = (const float*)d_in[5];
    const float* in_b_my  = (const float*)d_in[6];
    const float* out_w_my = (const float*)d_in[7];
    const float* out_b_my = (const float*)d_in[8];
    const float* in_w_op  = (const float*)d_in[9];
    const float* in_b_op  = (const float*)d_in[10];
    const float* out_w_op = (const float*)d_in[11];
    const float* out_b_op = (const float*)d_in[12];
    const float* w1       = (const float*)d_in[13];
    const float* b1       = (const float*)d_in[14];
    const float* ln_g     = (const float*)d_in[15];
    const float* ln_b     = (const float*)d_in[16];
    const float* w2       = (const float*)d_in[17];
    const float* b2       = (const float*)d_in[18];
    const float* w3       = (const float*)d_in[19];
    const float* b3       = (const float*)d_in[20];

    float *emb, *P, *mean, *feat, *h1, *w2t;
    cudaGetSymbolAddress((void**)&emb,  g_emb);
    cudaGetSymbolAddress((void**)&P,    g_P);
    cudaGetSymbolAddress((void**)&mean, g_mean);
    cudaGetSymbolAddress((void**)&feat, g_feat);
    cudaGetSymbolAddress((void**)&h1,   g_h1);
    cudaGetSymbolAddress((void**)&w2t,  g_w2t);

    // K1: embeddings
    emb_kernel<<<(NCARDS * 128 + 255) / 256, 256>>>(x_real, x_imag);

    // K2: per-card projection table P[10000][1536] (two N=768 GEMMs into column halves)
    dim3 gP(6, (NCARDS + 127) / 128);
    sgemm_tn<<<gP, 256>>>(emb, in_w_my, in_b_my, P,       NCARDS, 768, 256, 256, 256, 1536);
    sgemm_tn<<<gP, 256>>>(emb, in_w_op, in_b_op, P + 768, NCARDS, 768, 256, 256, 256, 1536);

    // K3: attention (mean-collapsed) -> g_mean[B][512]
    attn_kernel<<<BATCH, 256>>>(my_decks, op_decks, adj, P, mean);

    // K4: output projections -> g_feat[B][512]
    dim3 gF(2, BATCH / 128);
    sgemm_tn<<<gF, 256>>>(mean,       out_w_my, out_b_my, feat,       BATCH, 256, 256, 512, 256, 512);
    sgemm_tn<<<gF, 256>>>(mean + 256, out_w_op, out_b_op, feat + 256, BATCH, 256, 256, 512, 256, 512);

    // K5: h1 = feat @ w1^T + b1
    sgemm_tn<<<gF, 256>>>(feat, w1, b1, h1, BATCH, 256, 512, 512, 512, 256);

    // K6: LayerNorm + ReLU (in place)
    ln_relu_kernel<<<BATCH / 8, 256>>>(h1, ln_g, ln_b);

    // K7/K8: fc2 + relu + fc3 -> logits
    w2t_kernel<<<64, 256>>>(w2);
    head_kernel<<<BATCH / 16, 256>>>(h1, w2t, b2, w3, b3, (float*)d_out);
}

// round 2
// speedup vs baseline: 1.2782x; 1.2782x over previous
#include <cuda_runtime.h>
#include <math.h>

#define NCARDS 10000
#define BATCH  16384

// ---------------- scratch (static device globals; no allocation) ----------------
__device__ float g_emb [NCARDS * 256];      // [amp(128) | ph(128)] per card
__device__ float g_P   [NCARDS * 1536];     // per-card projections: [q_my k_my v_my q_op k_op v_op]
__device__ float g_mean[BATCH * 512];       // [mean_attn_my(256) | mean_attn_op(256)] pre-out-proj
__device__ float g_h1  [BATCH * 256];       // after combined w1 (LN applied in place)
__device__ float g_wc  [256 * 512];         // combined weight: [w1a@Wmy | w1b@Wop] row-major [256][512]
__device__ float g_bc  [256];               // combined bias
__device__ float g_w2t [256 * 64];          // w2 transposed (k-major)

// ---------------- K1: card embeddings ----------------
__global__ void emb_kernel(const float* __restrict__ xr, const float* __restrict__ xi) {
    int idx = blockIdx.x * 256 + threadIdx.x;
    if (idx >= NCARDS * 128) return;
    int c = idx >> 7, d = idx & 127;
    float a = xr[idx], b = xi[idx];
    g_emb[c * 256 + d]       = sqrtf(a * a + b * b + 1e-8f);
    g_emb[c * 256 + 128 + d] = atan2f(b, a);
}

// ---------------- combined weight build: wc[n][half*256+k] = sum_j w1[n][half*256+j] * W[j][k] ----------------
__global__ void build_wc_kernel(const float* __restrict__ w1, const float* __restrict__ wmy,
                                const float* __restrict__ wop, float* __restrict__ wc) {
    int k = threadIdx.x;                 // 0..255
    int half = blockIdx.y;               // 0=my, 1=op
    int n0 = blockIdx.x * 16;
    const float* W = half ? wop : wmy;
    float acc[16];
#pragma unroll
    for (int i = 0; i < 16; i++) acc[i] = 0.f;
    for (int j = 0; j < 256; j++) {
        float wv = W[j * 256 + k];
#pragma unroll
        for (int i = 0; i < 16; i++)
            acc[i] += w1[(size_t)(n0 + i) * 512 + half * 256 + j] * wv;
    }
#pragma unroll
    for (int i = 0; i < 16; i++)
        wc[(size_t)(n0 + i) * 512 + half * 256 + k] = acc[i];
}

__global__ void build_bc_kernel(const float* __restrict__ b1, const float* __restrict__ w1,
                                const float* __restrict__ bmy, const float* __restrict__ bop,
                                float* __restrict__ bc) {
    int n = threadIdx.x;                 // 256 threads, 1 block
    float acc = b1[n];
    for (int j = 0; j < 256; j++) {
        acc += w1[(size_t)n * 512 + j]       * bmy[j];
        acc += w1[(size_t)n * 512 + 256 + j] * bop[j];
    }
    bc[n] = acc;
}

// ---------------- generic fp32 GEMM: C[M,N] = A[M,K] * B[N,K]^T + bias[N] ----------------
// 128x128 tile, BK=16, 256 threads, 8x8 per thread
__global__ void sgemm_tn(const float* __restrict__ A, const float* __restrict__ B,
                         const float* __restrict__ bias, float* __restrict__ C,
                         int M, int N, int K, int lda, int ldb, int ldc) {
    __shared__ float sA[16][132];
    __shared__ float sB[16][132];
    int tid = threadIdx.x;
    int ty = tid >> 4, tx = tid & 15;
    int bm = blockIdx.y * 128, bn = blockIdx.x * 128;
    int lr = tid >> 2, seg = tid & 3;    // lr: 0..63, seg: k-chunk

    float acc[8][8];
#pragma unroll
    for (int i = 0; i < 8; i++)
#pragma unroll
        for (int j = 0; j < 8; j++) acc[i][j] = 0.f;

    for (int k0 = 0; k0 < K; k0 += 16) {
        float4 z = make_float4(0.f, 0.f, 0.f, 0.f);
        float4 va0 = z, va1 = z, vb0 = z, vb1 = z;
        int ar0 = bm + lr, ar1 = bm + lr + 64;
        if (ar0 < M) va0 = *(const float4*)&A[(size_t)ar0 * lda + k0 + seg * 4];
        if (ar1 < M) va1 = *(const float4*)&A[(size_t)ar1 * lda + k0 + seg * 4];
        int br0 = bn + lr, br1 = bn + lr + 64;
        if (br0 < N) vb0 = *(const float4*)&B[(size_t)br0 * ldb + k0 + seg * 4];
        if (br1 < N) vb1 = *(const float4*)&B[(size_t)br1 * ldb + k0 + seg * 4];
        __syncthreads();   // previous iteration's compute done
        sA[seg * 4 + 0][lr] = va0.x; sA[seg * 4 + 1][lr] = va0.y;
        sA[seg * 4 + 2][lr] = va0.z; sA[seg * 4 + 3][lr] = va0.w;
        sA[seg * 4 + 0][lr + 64] = va1.x; sA[seg * 4 + 1][lr + 64] = va1.y;
        sA[seg * 4 + 2][lr + 64] = va1.z; sA[seg * 4 + 3][lr + 64] = va1.w;
        sB[seg * 4 + 0][lr] = vb0.x; sB[seg * 4 + 1][lr] = vb0.y;
        sB[seg * 4 + 2][lr] = vb0.z; sB[seg * 4 + 3][lr] = vb0.w;
        sB[seg * 4 + 0][lr + 64] = vb1.x; sB[seg * 4 + 1][lr + 64] = vb1.y;
        sB[seg * 4 + 2][lr + 64] = vb1.z; sB[seg * 4 + 3][lr + 64] = vb1.w;
        __syncthreads();
#pragma unroll
        for (int k = 0; k < 16; k++) {
            float4 a0 = *(const float4*)&sA[k][ty * 8];
            float4 a1 = *(const float4*)&sA[k][ty * 8 + 4];
            float4 b0 = *(const float4*)&sB[k][tx * 8];
            float4 b1 = *(const float4*)&sB[k][tx * 8 + 4];
            float av[8] = {a0.x, a0.y, a0.z, a0.w, a1.x, a1.y, a1.z, a1.w};
            float bv[8] = {b0.x, b0.y, b0.z, b0.w, b1.x, b1.y, b1.z, b1.w};
#pragma unroll
            for (int i = 0; i < 8; i++)
#pragma unroll
                for (int j = 0; j < 8; j++) acc[i][j] += av[i] * bv[j];
        }
    }
#pragma unroll
    for (int i = 0; i < 8; i++) {
        int row = bm + ty * 8 + i;
        if (row >= M) continue;
#pragma unroll
        for (int j = 0; j < 8; j++) {
            int col = bn + tx * 8 + j;
            if (col < N) C[(size_t)row * ldc + col] = acc[i][j] + bias[col];
        }
    }
}

// ---------------- K3: per-batch dual cross-attention, mean-collapsed ----------------
// Padded smem rows (260 floats) -> conflict-free score loads.
#define RP 260
__global__ void attn_kernel(const int* __restrict__ my_decks, const int* __restrict__ op_decks,
                            const int* __restrict__ adj, const float* __restrict__ P,
                            float* __restrict__ meanout) {
    __shared__ int   sMy[8], sOp[8];
    __shared__ float sMat[4][8][RP];    // 0:Q_A 1:Q_B 2:K_A 3:K_B   (~33 KB)
    __shared__ float sBias[8][8];
    __shared__ float sS[2][4][8][8];
    __shared__ float sW[2][4][8];

    int b = blockIdx.x, t = threadIdx.x;
    if (t < 8)        sMy[t]     = my_decks[b * 8 + t];
    else if (t < 16)  sOp[t - 8] = op_decks[b * 8 + (t - 8)];
    __syncthreads();

    if (t < 64) {
        int i = t >> 3, j = t & 7;
        sBias[i][j] = (adj[(size_t)sMy[i] * NCARDS + sOp[j]] > 0) ? 0.f : -10000.f;
    }

    // gather Q/K rows (4 mats x 8 rows x 256 floats = 2048 float4)
    const int offs[4] = {0, 768, 256, 1024};
#pragma unroll
    for (int it = 0; it < 8; it++) {
        int idx  = t + it * 256;          // 0..2047
        int row  = idx >> 6;              // 0..31
        int c4   = idx & 63;
        int mat  = row >> 3, slot = row & 7;
        int card = (mat == 0 || mat == 3) ? sMy[slot] : sOp[slot];
        float4 v = *(const float4*)&P[(size_t)card * 1536 + offs[mat] + c4 * 4];
        ((float4*)&sMat[mat][slot][0])[c4] = v;
    }
    __syncthreads();

    // scores: 512 dot-products of length 64; 2 per thread sharing the Q row
    {
        int s  = t >> 7;
        int h  = (t >> 5) & 3;
        int a  = (t >> 2) & 7;
        int b0 = (t & 3) * 2;
        const float* q  = &sMat[s][a][h * 64];
        const float* k0 = &sMat[2 + s][b0][h * 64];
        const float* k1 = &sMat[2 + s][b0 + 1][h * 64];
        float d0 = 0.f, d1 = 0.f;
#pragma unroll
        for (int d = 0; d < 64; d += 4) {
            float4 qv  = *(const float4*)&q[d];
            float4 kv0 = *(const float4*)&k0[d];
            float4 kv1 = *(const float4*)&k1[d];
            d0 += qv.x * kv0.x + qv.y * kv0.y + qv.z * kv0.z + qv.w * kv0.w;
            d1 += qv.x * kv1.x + qv.y * kv1.y + qv.z * kv1.z + qv.w * kv1.w;
        }
        float bi0 = (s == 0) ? sBias[a][b0]     : sBias[b0][a];
        float bi1 = (s == 0) ? sBias[a][b0 + 1] : sBias[b0 + 1][a];
        sS[s][h][a][b0]     = d0 * 0.125f + bi0;
        sS[s][h][a][b0 + 1] = d1 * 0.125f + bi1;
    }
    __syncthreads();

    // softmax over keys (rows of 8)
    if (t < 64) {
        int s = t >> 5, h = (t >> 3) & 3, a = t & 7;
        float* row = &sS[s][h][a][0];
        float m = row[0];
#pragma unroll
        for (int j = 1; j < 8; j++) m = fmaxf(m, row[j]);
        float p[8], sum = 0.f;
#pragma unroll
        for (int j = 0; j < 8; j++) { p[j] = __expf(row[j] - m); sum += p[j]; }
        float inv = 1.f / sum;
#pragma unroll
        for (int j = 0; j < 8; j++) row[j] = p[j] * inv;
    }
    __syncthreads();

    // mean-collapsed weights: w[s][h][j] = (1/8) * sum_a p[s][h][a][j]
    if (t < 64) {
        int s = t >> 5, h = (t >> 3) & 3, bb = t & 7;
        float w = 0.f;
#pragma unroll
        for (int a = 0; a < 8; a++) w += sS[s][h][a][bb];
        sW[s][h][bb] = w * 0.125f;
    }
    __syncthreads();

    // output: each thread handles one side and 2 consecutive dims; V read from L2
    {
        int s  = t >> 7;
        int d0 = (t & 127) * 2;
        int h  = d0 >> 6;
        int off = (s == 0) ? 512 : 1280;
        float w[8];
#pragma unroll
        for (int j = 0; j < 8; j++) w[j] = sW[s][h][j];
        float acc0 = 0.f, acc1 = 0.f;
#pragma unroll
        for (int j = 0; j < 8; j++) {
            int card = (s == 0) ? sOp[j] : sMy[j];
            float2 v = *(const float2*)&P[(size_t)card * 1536 + off + d0];
            acc0 += w[j] * v.x; acc1 += w[j] * v.y;
        }
        *(float2*)&meanout[(size_t)b * 512 + s * 256 + d0] = make_float2(acc0, acc1);
    }
}

// ---------------- K6: LayerNorm + ReLU, in place, one warp per row of 256 ----------------
__global__ void ln_relu_kernel(float* __restrict__ h, const float* __restrict__ g,
                               const float* __restrict__ be) {
    int w = threadIdx.x >> 5, lane = threadIdx.x & 31;
    int row = blockIdx.x * 8 + w;
    float* rp = h + (size_t)row * 256;
    float4 v0 = *(float4*)&rp[lane * 8];
    float4 v1 = *(float4*)&rp[lane * 8 + 4];
    float vals[8] = {v0.x, v0.y, v0.z, v0.w, v1.x, v1.y, v1.z, v1.w};
    float s = 0.f, sq = 0.f;
#pragma unroll
    for (int q = 0; q < 8; q++) { s += vals[q]; sq += vals[q] * vals[q]; }
#pragma unroll
    for (int o = 16; o; o >>= 1) {
        s  += __shfl_xor_sync(0xffffffffu, s,  o);
        sq += __shfl_xor_sync(0xffffffffu, sq, o);
    }
    float mu   = s * (1.f / 256.f);
    float var  = sq * (1.f / 256.f) - mu * mu;
    float rstd = rsqrtf(var + 1e-5f);
#pragma unroll
    for (int q = 0; q < 8; q++) {
        int idx = lane * 8 + q;
        vals[q] = fmaxf(0.f, (vals[q] - mu) * rstd * g[idx] + be[idx]);
    }
    *(float4*)&rp[lane * 8]     = make_float4(vals[0], vals[1], vals[2], vals[3]);
    *(float4*)&rp[lane * 8 + 4] = make_float4(vals[4], vals[5], vals[6], vals[7]);
}

// ---------------- w2 transpose (k-major for coalesced head reads) ----------------
__global__ void w2t_kernel(const float* __restrict__ w2) {
    int idx = blockIdx.x * 256 + threadIdx.x;   // 64*256 = 16384
    int n = idx >> 8, k = idx & 255;
    g_w2t[k * 64 + n] = w2[idx];
}

// ---------------- K7/K8: fc2 + relu + fc3, 16 rows per block ----------------
__global__ void head_kernel(const float* __restrict__ h, const float* __restrict__ w2t,
                            const float* __restrict__ b2, const float* __restrict__ w3,
                            const float* __restrict__ b3, float* __restrict__ out) {
    __shared__ float sH[4][256];
    __shared__ float sPart[4][2];
    int t = threadIdx.x;
    int rsub = t >> 6, n = t & 63, lane = t & 31;
    float b2n = b2[n], w3n = w3[n], b3v = b3[0];

    for (int it = 0; it < 4; it++) {
        __syncthreads();   // protect previous iteration's sH/sPart readers
#pragma unroll
        for (int q = 0; q < 4; q++) {
            int fi = t + q * 256;               // 0..1023
            int rr = fi >> 8, cc = fi & 255;
            sH[rr][cc] = h[(size_t)(blockIdx.x * 16 + it * 4 + rr) * 256 + cc];
        }
        __syncthreads();
        float acc = 0.f;
#pragma unroll 8
        for (int k = 0; k < 256; k++) acc += sH[rsub][k] * w2t[k * 64 + n];
        float p = fmaxf(acc + b2n, 0.f) * w3n;
#pragma unroll
        for (int o = 16; o; o >>= 1) p += __shfl_xor_sync(0xffffffffu, p, o);
        if (lane == 0) sPart[rsub][(t >> 5) & 1] = p;
        __syncthreads();
        if (t < 4) out[blockIdx.x * 16 + it * 4 + t] = sPart[t][0] + sPart[t][1] + b3v;
    }
}

// ---------------- launch ----------------
extern "C" void kernel_launch(void* const* d_in, const int* in_sizes, int n_in,
                              void* d_out, int out_size) {
    (void)in_sizes; (void)n_in; (void)out_size;
    const float* x_real   = (const float*)d_in[0];
    const float* x_imag   = (const float*)d_in[1];
    const int*   my_decks = (const int*)  d_in[2];
    const int*   op_decks = (const int*)  d_in[3];
    const int*   adj      = (const int*)  d_in[4];
    const float* in_w_my  = (const float*)d_in[5];
    const float* in_b_my  = (const float*)d_in[6];
    const float* out_w_my = (const float*)d_in[7];
    const float* out_b_my = (const float*)d_in[8];
    const float* in_w_op  = (const float*)d_in[9];
    const float* in_b_op  = (const float*)d_in[10];
    const float* out_w_op = (const float*)d_in[11];
    const float* out_b_op = (const float*)d_in[12];
    const float* w1       = (const float*)d_in[13];
    const float* b1       = (const float*)d_in[14];
    const float* ln_g     = (const float*)d_in[15];
    const float* ln_b     = (const float*)d_in[16];
    const float* w2       = (const float*)d_in[17];
    const float* b2       = (const float*)d_in[18];
    const float* w3       = (const float*)d_in[19];
    const float* b3       = (const float*)d_in[20];

    float *emb, *P, *mean, *h1, *wc, *bc, *w2t;
    cudaGetSymbolAddress((void**)&emb,  g_emb);
    cudaGetSymbolAddress((void**)&P,    g_P);
    cudaGetSymbolAddress((void**)&mean, g_mean);
    cudaGetSymbolAddress((void**)&h1,   g_h1);
    cudaGetSymbolAddress((void**)&wc,   g_wc);
    cudaGetSymbolAddress((void**)&bc,   g_bc);
    cudaGetSymbolAddress((void**)&w2t,  g_w2t);

    // K1: embeddings
    emb_kernel<<<(NCARDS * 128 + 255) / 256, 256>>>(x_real, x_imag);

    // Combined out-proj+w1 weight (removes both out-projection GEMMs)
    build_wc_kernel<<<dim3(16, 2), 256>>>(w1, out_w_my, out_w_op, wc);
    build_bc_kernel<<<1, 256>>>(b1, w1, out_b_my, out_b_op, bc);
    w2t_kernel<<<64, 256>>>(w2);

    // K2: per-card projection table P[10000][1536]
    dim3 gP(6, (NCARDS + 127) / 128);
    sgemm_tn<<<gP, 256>>>(emb, in_w_my, in_b_my, P,       NCARDS, 768, 256, 256, 256, 1536);
    sgemm_tn<<<gP, 256>>>(emb, in_w_op, in_b_op, P + 768, NCARDS, 768, 256, 256, 256, 1536);

    // K3: attention (mean-collapsed) -> g_mean[B][512]
    attn_kernel<<<BATCH, 256>>>(my_decks, op_decks, adj, P, mean);

    // K5': h1 = mean @ wc^T + bc   (out-projections folded into wc)
    dim3 gF(2, BATCH / 128);
    sgemm_tn<<<gF, 256>>>(mean, wc, bc, h1, BATCH, 256, 512, 512, 512, 256);

    // K6: LayerNorm + ReLU (in place)
    ln_relu_kernel<<<BATCH / 8, 256>>>(h1, ln_g, ln_b);

    // K7/K8: fc2 + relu + fc3 -> logits
    head_kernel<<<BATCH / 16, 256>>>(h1, w2t, b2, w3, b3, (float*)d_out);
}

// round 4
// speedup vs baseline: 1.7415x; 1.3624x over previous
#include <cuda_runtime.h>
#include <cuda_bf16.h>
#include <cstdint>
#include <math.h>

#define NCARDS 10000
#define BATCH  16384

// ---------------- scratch (static device globals; no allocation) ----------------
__device__ __nv_bfloat16 g_embh[NCARDS * 256];   // emb hi
__device__ __nv_bfloat16 g_embl[NCARDS * 256];   // emb lo
__device__ __nv_bfloat16 g_iwh [2 * 768 * 256];  // in_w (my|op) hi
__device__ __nv_bfloat16 g_iwl [2 * 768 * 256];  // in_w (my|op) lo
__device__ float         g_P   [NCARDS * 1536];  // per-card projections
__device__ __nv_bfloat16 g_meanh[BATCH * 512];   // mean attn hi
__device__ __nv_bfloat16 g_meanl[BATCH * 512];   // mean attn lo
__device__ __nv_bfloat16 g_wch [256 * 512];      // combined weight hi
__device__ __nv_bfloat16 g_wcl [256 * 512];      // combined weight lo
__device__ float         g_bc  [256];            // combined bias
__device__ float         g_h1  [BATCH * 256];    // after w1 (LN in place)
__device__ float         g_w2t [256 * 64];       // w2 transposed

// ---------------- helpers ----------------
__device__ __forceinline__ uint32_t smem_u32(const void* p) {
    uint32_t a;
    asm("{ .reg .u64 t; cvta.to.shared.u64 t, %1; cvt.u32.u64 %0, t; }" : "=r"(a) : "l"(p));
    return a;
}
__device__ __forceinline__ void split_bf(float f, __nv_bfloat16& h, __nv_bfloat16& l) {
    h = __float2bfloat16_rn(f);
    l = __float2bfloat16_rn(f - __bfloat162float(h));
}

#define LDMX4(r, a) asm volatile("ldmatrix.sync.aligned.m8n8.x4.shared.b16 {%0,%1,%2,%3}, [%4];" \
    : "=r"((r)[0]), "=r"((r)[1]), "=r"((r)[2]), "=r"((r)[3]) : "r"(a))
#define LDMX2(r, a) asm volatile("ldmatrix.sync.aligned.m8n8.x2.shared.b16 {%0,%1}, [%2];" \
    : "=r"((r)[0]), "=r"((r)[1]) : "r"(a))

__device__ __forceinline__ void mma_bf16(float* d, const uint32_t* a, const uint32_t* b) {
    asm volatile("mma.sync.aligned.m16n8k16.row.col.f32.bf16.bf16.f32 "
        "{%0,%1,%2,%3}, {%4,%5,%6,%7}, {%8,%9}, {%0,%1,%2,%3};"
        : "+f"(d[0]), "+f"(d[1]), "+f"(d[2]), "+f"(d[3])
        : "r"(a[0]), "r"(a[1]), "r"(a[2]), "r"(a[3]), "r"(b[0]), "r"(b[1]));
}

// ================= split-bf16 tensor GEMM via mma.sync =================
// C[M,N] = (Ah+Al)[M,K] @ (Bh+Bl)[N,K]^T + bias[N]  (3-term product)
// tile 128x128, K-chunk 64, 256 threads (8 warps, 2x4), warp tile 64x32.
// smem: 4 tiles of 128 rows x 72 bf16 (pitch 144B, 16B-aligned, ldmatrix conflict-free)
#define TG_PITCH   144
#define TG_TILE    18432
#define TG_SMEM   (4 * TG_TILE)

__global__ void tgemm(const __nv_bfloat16* __restrict__ Ah, const __nv_bfloat16* __restrict__ Al,
                      const __nv_bfloat16* __restrict__ Bh, const __nv_bfloat16* __restrict__ Bl,
                      const float* __restrict__ bias, float* __restrict__ C,
                      int M, int K, int lda, int ldb, int ldc) {
    extern __shared__ char smem[];
    uint32_t sb = smem_u32(smem);
    int t = threadIdx.x, wid = t >> 5, lane = t & 31;
    int bm = blockIdx.y * 128, bn = blockIdx.x * 128;
    int warpM = (wid & 1) * 64, warpN = (wid >> 1) * 32;

    const uint32_t oAh = 0, oAl = TG_TILE, oBh = 2 * TG_TILE, oBl = 3 * TG_TILE;

    float acc[4][4][4];
#pragma unroll
    for (int i = 0; i < 4; i++)
#pragma unroll
        for (int j = 0; j < 4; j++)
#pragma unroll
            for (int q = 0; q < 4; q++) acc[i][j][q] = 0.f;

    int row = t >> 1, half = t & 1;                 // 128 rows x 2 halves
    bool aok = (bm + row) < M;
    const __nv_bfloat16* ArH = Ah + (size_t)(bm + row) * lda;
    const __nv_bfloat16* ArL = Al + (size_t)(bm + row) * lda;
    const __nv_bfloat16* BrH = Bh + (size_t)(bn + row) * ldb;
    const __nv_bfloat16* BrL = Bl + (size_t)(bn + row) * ldb;
    uint32_t dstA = row * TG_PITCH + half * 64;     // 32 bf16 = 64 bytes per half
    int nch = K >> 6;

    for (int c = 0; c < nch; c++) {
        int k0 = c * 64 + half * 32;
        __syncthreads();   // previous chunk's compute done before overwrite
        uint4 z = make_uint4(0, 0, 0, 0);
#pragma unroll
        for (int g = 0; g < 4; g++) {
            uint4 vh = aok ? *(const uint4*)&ArH[k0 + g * 8] : z;
            uint4 vl = aok ? *(const uint4*)&ArL[k0 + g * 8] : z;
            *(uint4*)(smem + oAh + dstA + g * 16) = vh;
            *(uint4*)(smem + oAl + dstA + g * 16) = vl;
            uint4 wh = *(const uint4*)&BrH[k0 + g * 8];
            uint4 wl = *(const uint4*)&BrL[k0 + g * 8];
            *(uint4*)(smem + oBh + dstA + g * 16) = wh;
            *(uint4*)(smem + oBl + dstA + g * 16) = wl;
        }
        __syncthreads();

#pragma unroll
        for (int ks = 0; ks < 4; ks++) {
            uint32_t bh[4][2], bl[4][2];
#pragma unroll
            for (int j = 0; j < 4; j++) {
                uint32_t ab = sb + oBh + (warpN + j * 8 + (lane & 7)) * TG_PITCH
                            + ks * 32 + ((lane >> 3) & 1) * 16;
                LDMX2(bh[j], ab);
                LDMX2(bl[j], ab + (oBl - oBh));
            }
#pragma unroll
            for (int i = 0; i < 4; i++) {
                uint32_t aa = sb + oAh + (warpM + i * 16 + (lane & 15)) * TG_PITCH
                            + ks * 32 + (lane >> 4) * 16;
                uint32_t ah[4], al[4];
                LDMX4(ah, aa);
                LDMX4(al, aa + (oAl - oAh));
#pragma unroll
                for (int j = 0; j < 4; j++) {
                    mma_bf16(acc[i][j], ah, bh[j]);
                    mma_bf16(acc[i][j], ah, bl[j]);
                    mma_bf16(acc[i][j], al, bh[j]);
                }
            }
        }
    }

    // epilogue: fragment -> gmem with bias
#pragma unroll
    for (int i = 0; i < 4; i++) {
        int r0 = bm + warpM + i * 16 + (lane >> 2);
#pragma unroll
        for (int j = 0; j < 4; j++) {
            int cN = bn + warpN + j * 8 + (lane & 3) * 2;
            float b0 = bias[cN], b1 = bias[cN + 1];
            if (r0 < M)
                *(float2*)&C[(size_t)r0 * ldc + cN] =
                    make_float2(acc[i][j][0] + b0, acc[i][j][1] + b1);
            if (r0 + 8 < M)
                *(float2*)&C[(size_t)(r0 + 8) * ldc + cN] =
                    make_float2(acc[i][j][2] + b0, acc[i][j][3] + b1);
        }
    }
}

// ---------------- K1: card embeddings (split-bf16 output) ----------------
__global__ void emb_kernel(const float* __restrict__ xr, const float* __restrict__ xi) {
    int idx = blockIdx.x * 256 + threadIdx.x;
    if (idx >= NCARDS * 128) return;
    int c = idx >> 7, d = idx & 127;
    float a = xr[idx], b = xi[idx];
    float amp = sqrtf(a * a + b * b + 1e-8f);
    float ph  = atan2f(b, a);
    __nv_bfloat16 h, l;
    split_bf(amp, h, l);
    g_embh[c * 256 + d] = h; g_embl[c * 256 + d] = l;
    split_bf(ph, h, l);
    g_embh[c * 256 + 128 + d] = h; g_embl[c * 256 + 128 + d] = l;
}

// ---------------- elementwise split ----------------
__global__ void split_kernel(const float* __restrict__ src, __nv_bfloat16* __restrict__ dh,
                             __nv_bfloat16* __restrict__ dl, int n) {
    int i = blockIdx.x * 256 + threadIdx.x;
    if (i >= n) return;
    __nv_bfloat16 h, l;
    split_bf(src[i], h, l);
    dh[i] = h; dl[i] = l;
}

// ---------------- combined weight build (split output) ----------------
__global__ void build_wc_kernel(const float* __restrict__ w1, const float* __restrict__ wmy,
                                const float* __restrict__ wop) {
    int k = threadIdx.x;
    int half = blockIdx.y;
    int n0 = blockIdx.x * 16;
    const float* W = half ? wop : wmy;
    float acc[16];
#pragma unroll
    for (int i = 0; i < 16; i++) acc[i] = 0.f;
    for (int j = 0; j < 256; j++) {
        float wv = W[j * 256 + k];
#pragma unroll
        for (int i = 0; i < 16; i++)
            acc[i] += w1[(size_t)(n0 + i) * 512 + half * 256 + j] * wv;
    }
#pragma unroll
    for (int i = 0; i < 16; i++) {
        __nv_bfloat16 h, l;
        split_bf(acc[i], h, l);
        size_t o = (size_t)(n0 + i) * 512 + half * 256 + k;
        g_wch[o] = h; g_wcl[o] = l;
    }
}

__global__ void build_bc_kernel(const float* __restrict__ b1, const float* __restrict__ w1,
                                const float* __restrict__ bmy, const float* __restrict__ bop) {
    int n = threadIdx.x;
    float acc = b1[n];
    for (int j = 0; j < 256; j++) {
        acc += w1[(size_t)n * 512 + j]       * bmy[j];
        acc += w1[(size_t)n * 512 + 256 + j] * bop[j];
    }
    g_bc[n] = acc;
}

// ---------------- K3: per-batch dual cross-attention, mean-collapsed ----------------
#define RP 260
__global__ void attn_kernel(const int* __restrict__ my_decks, const int* __restrict__ op_decks,
                            const int* __restrict__ adj, const float* __restrict__ P) {
    __shared__ int   sMy[8], sOp[8];
    __shared__ float sMat[4][8][RP];
    __shared__ float sBias[8][8];
    __shared__ float sS[2][4][8][8];
    __shared__ float sW[2][4][8];

    int b = blockIdx.x, t = threadIdx.x;
    if (t < 8)        sMy[t]     = my_decks[b * 8 + t];
    else if (t < 16)  sOp[t - 8] = op_decks[b * 8 + (t - 8)];
    __syncthreads();

    if (t < 64) {
        int i = t >> 3, j = t & 7;
        sBias[i][j] = (adj[(size_t)sMy[i] * NCARDS + sOp[j]] > 0) ? 0.f : -10000.f;
    }

    const int offs[4] = {0, 768, 256, 1024};
#pragma unroll
    for (int it = 0; it < 8; it++) {
        int idx  = t + it * 256;
        int row  = idx >> 6;
        int c4   = idx & 63;
        int mat  = row >> 3, slot = row & 7;
        int card = (mat == 0 || mat == 3) ? sMy[slot] : sOp[slot];
        float4 v = *(const float4*)&P[(size_t)card * 1536 + offs[mat] + c4 * 4];
        ((float4*)&sMat[mat][slot][0])[c4] = v;
    }
    __syncthreads();

    {
        int s  = t >> 7;
        int h  = (t >> 5) & 3;
        int a  = (t >> 2) & 7;
        int b0 = (t & 3) * 2;
        const float* q  = &sMat[s][a][h * 64];
        const float* k0 = &sMat[2 + s][b0][h * 64];
        const float* k1 = &sMat[2 + s][b0 + 1][h * 64];
        float d0 = 0.f, d1 = 0.f;
#pragma unroll
        for (int d = 0; d < 64; d += 4) {
            float4 qv  = *(const float4*)&q[d];
            float4 kv0 = *(const float4*)&k0[d];
            float4 kv1 = *(const float4*)&k1[d];
            d0 += qv.x * kv0.x + qv.y * kv0.y + qv.z * kv0.z + qv.w * kv0.w;
            d1 += qv.x * kv1.x + qv.y * kv1.y + qv.z * kv1.z + qv.w * kv1.w;
        }
        float bi0 = (s == 0) ? sBias[a][b0]     : sBias[b0][a];
        float bi1 = (s == 0) ? sBias[a][b0 + 1] : sBias[b0 + 1][a];
        sS[s][h][a][b0]     = d0 * 0.125f + bi0;
        sS[s][h][a][b0 + 1] = d1 * 0.125f + bi1;
    }
    __syncthreads();

    if (t < 64) {
        int s = t >> 5, h = (t >> 3) & 3, a = t & 7;
        float* row = &sS[s][h][a][0];
        float m = row[0];
#pragma unroll
        for (int j = 1; j < 8; j++) m = fmaxf(m, row[j]);
        float p[8], sum = 0.f;
#pragma unroll
        for (int j = 0; j < 8; j++) { p[j] = __expf(row[j] - m); sum += p[j]; }
        float inv = 1.f / sum;
#pragma unroll
        for (int j = 0; j < 8; j++) row[j] = p[j] * inv;
    }
    __syncthreads();

    if (t < 64) {
        int s = t >> 5, h = (t >> 3) & 3, bb = t & 7;
        float w = 0.f;
#pragma unroll
        for (int a = 0; a < 8; a++) w += sS[s][h][a][bb];
        sW[s][h][bb] = w * 0.125f;
    }
    __syncthreads();

    {
        int s  = t >> 7;
        int d0 = (t & 127) * 2;
        int h  = d0 >> 6;
        int off = (s == 0) ? 512 : 1280;
        float w[8];
#pragma unroll
        for (int j = 0; j < 8; j++) w[j] = sW[s][h][j];
        float acc0 = 0.f, acc1 = 0.f;
#pragma unroll
        for (int j = 0; j < 8; j++) {
            int card = (s == 0) ? sOp[j] : sMy[j];
            float2 v = *(const float2*)&P[(size_t)card * 1536 + off + d0];
            acc0 += w[j] * v.x; acc1 += w[j] * v.y;
        }
        // write split-bf16 directly (feeds the h1 tensor GEMM)
        __nv_bfloat16 h0, l0, h1, l1;
        split_bf(acc0, h0, l0);
        split_bf(acc1, h1, l1);
        size_t o = (size_t)b * 512 + s * 256 + d0;
        *(__nv_bfloat162*)&g_meanh[o] = __nv_bfloat162(h0, h1);
        *(__nv_bfloat162*)&g_meanl[o] = __nv_bfloat162(l0, l1);
    }
}

// ---------------- K6: LayerNorm + ReLU ----------------
__global__ void ln_relu_kernel(float* __restrict__ h, const float* __restrict__ g,
                               const float* __restrict__ be) {
    int w = threadIdx.x >> 5, lane = threadIdx.x & 31;
    int row = blockIdx.x * 8 + w;
    float* rp = h + (size_t)row * 256;
    float4 v0 = *(float4*)&rp[lane * 8];
    float4 v1 = *(float4*)&rp[lane * 8 + 4];
    float vals[8] = {v0.x, v0.y, v0.z, v0.w, v1.x, v1.y, v1.z, v1.w};
    float s = 0.f, sq = 0.f;
#pragma unroll
    for (int q = 0; q < 8; q++) { s += vals[q]; sq += vals[q] * vals[q]; }
#pragma unroll
    for (int o = 16; o; o >>= 1) {
        s  += __shfl_xor_sync(0xffffffffu, s,  o);
        sq += __shfl_xor_sync(0xffffffffu, sq, o);
    }
    float mu   = s * (1.f / 256.f);
    float var  = sq * (1.f / 256.f) - mu * mu;
    float rstd = rsqrtf(var + 1e-5f);
#pragma unroll
    for (int q = 0; q < 8; q++) {
        int idx = lane * 8 + q;
        vals[q] = fmaxf(0.f, (vals[q] - mu) * rstd * g[idx] + be[idx]);
    }
    *(float4*)&rp[lane * 8]     = make_float4(vals[0], vals[1], vals[2], vals[3]);
    *(float4*)&rp[lane * 8 + 4] = make_float4(vals[4], vals[5], vals[6], vals[7]);
}

// ---------------- w2 transpose ----------------
__global__ void w2t_kernel(const float* __restrict__ w2) {
    int idx = blockIdx.x * 256 + threadIdx.x;
    int n = idx >> 8, k = idx & 255;
    g_w2t[k * 64 + n] = w2[idx];
}

// ---------------- K7/K8: fc2 + relu + fc3 ----------------
__global__ void head_kernel(const float* __restrict__ h, const float* __restrict__ w2t,
                            const float* __restrict__ b2, const float* __restrict__ w3,
                            const float* __restrict__ b3, float* __restrict__ out) {
    __shared__ float sH[4][256];
    __shared__ float sPart[4][2];
    int t = threadIdx.x;
    int rsub = t >> 6, n = t & 63, lane = t & 31;
    float b2n = b2[n], w3n = w3[n], b3v = b3[0];

    for (int it = 0; it < 4; it++) {
        __syncthreads();
#pragma unroll
        for (int q = 0; q < 4; q++) {
            int fi = t + q * 256;
            int rr = fi >> 8, cc = fi & 255;
            sH[rr][cc] = h[(size_t)(blockIdx.x * 16 + it * 4 + rr) * 256 + cc];
        }
        __syncthreads();
        float acc = 0.f;
#pragma unroll 8
        for (int k = 0; k < 256; k++) acc += sH[rsub][k] * w2t[k * 64 + n];
        float p = fmaxf(acc + b2n, 0.f) * w3n;
#pragma unroll
        for (int o = 16; o; o >>= 1) p += __shfl_xor_sync(0xffffffffu, p, o);
        if (lane == 0) sPart[rsub][(t >> 5) & 1] = p;
        __syncthreads();
        if (t < 4) out[blockIdx.x * 16 + it * 4 + t] = sPart[t][0] + sPart[t][1] + b3v;
    }
}

// ---------------- launch ----------------
extern "C" void kernel_launch(void* const* d_in, const int* in_sizes, int n_in,
                              void* d_out, int out_size) {
    (void)in_sizes; (void)n_in; (void)out_size;
    const float* x_real   = (const float*)d_in[0];
    const float* x_imag   = (const float*)d_in[1];
    const int*   my_decks = (const int*)  d_in[2];
    const int*   op_decks = (const int*)  d_in[3];
    const int*   adj      = (const int*)  d_in[4];
    const float* in_w_my  = (const float*)d_in[5];
    const float* in_b_my  = (const float*)d_in[6];
    const float* out_w_my = (const float*)d_in[7];
    const float* out_b_my = (const float*)d_in[8];
    const float* in_w_op  = (const float*)d_in[9];
    const float* in_b_op  = (const float*)d_in[10];
    const float* out_w_op = (const float*)d_in[11];
    const float* out_b_op = (const float*)d_in[12];
    const float* w1       = (const float*)d_in[13];
    const float* b1       = (const float*)d_in[14];
    const float* ln_g     = (const float*)d_in[15];
    const float* ln_b     = (const float*)d_in[16];
    const float* w2       = (const float*)d_in[17];
    const float* b2       = (const float*)d_in[18];
    const float* w3       = (const float*)d_in[19];
    const float* b3       = (const float*)d_in[20];

    __nv_bfloat16 *embh, *embl, *iwh, *iwl, *meanh, *meanl, *wch, *wcl;
    float *P, *bc, *h1, *w2t;
    cudaGetSymbolAddress((void**)&embh,  g_embh);
    cudaGetSymbolAddress((void**)&embl,  g_embl);
    cudaGetSymbolAddress((void**)&iwh,   g_iwh);
    cudaGetSymbolAddress((void**)&iwl,   g_iwl);
    cudaGetSymbolAddress((void**)&P,     g_P);
    cudaGetSymbolAddress((void**)&meanh, g_meanh);
    cudaGetSymbolAddress((void**)&meanl, g_meanl);
    cudaGetSymbolAddress((void**)&wch,   g_wch);
    cudaGetSymbolAddress((void**)&wcl,   g_wcl);
    cudaGetSymbolAddress((void**)&bc,    g_bc);
    cudaGetSymbolAddress((void**)&h1,    g_h1);
    cudaGetSymbolAddress((void**)&w2t,   g_w2t);

    cudaFuncSetAttribute(tgemm, cudaFuncAttributeMaxDynamicSharedMemorySize, TG_SMEM);

    // K1: embeddings (split-bf16)
    emb_kernel<<<(NCARDS * 128 + 255) / 256, 256>>>(x_real, x_imag);

    // split in_w matrices
    split_kernel<<<(768 * 256 + 255) / 256, 256>>>(in_w_my, iwh,             iwl,             768 * 256);
    split_kernel<<<(768 * 256 + 255) / 256, 256>>>(in_w_op, iwh + 768 * 256, iwl + 768 * 256, 768 * 256);

    // combined out-proj + w1 weight (split output)
    build_wc_kernel<<<dim3(16, 2), 256>>>(w1, out_w_my, out_w_op);
    build_bc_kernel<<<1, 256>>>(b1, w1, out_b_my, out_b_op);
    w2t_kernel<<<64, 256>>>(w2);

    // K2: per-card projection table P[10000][1536] (tensor mma.sync, split-bf16)
    dim3 gP(6, (NCARDS + 127) / 128);
    tgemm<<<gP, 256, TG_SMEM>>>(embh, embl, iwh,             iwl,             in_b_my, P,       NCARDS, 256, 256, 256, 1536);
    tgemm<<<gP, 256, TG_SMEM>>>(embh, embl, iwh + 768 * 256, iwl + 768 * 256, in_b_op, P + 768, NCARDS, 256, 256, 256, 1536);

    // K3: attention (mean-collapsed), writes split-bf16 mean
    attn_kernel<<<BATCH, 256>>>(my_decks, op_decks, adj, P);

    // K5': h1 = mean @ wc^T + bc (tensor mma.sync)
    dim3 gF(2, BATCH / 128);
    tgemm<<<gF, 256, TG_SMEM>>>(meanh, meanl, wch, wcl, bc, h1, BATCH, 512, 512, 512, 256);

    // K6: LayerNorm + ReLU (in place)
    ln_relu_kernel<<<BATCH / 8, 256>>>(h1, ln_g, ln_b);

    // K7/K8: fc2 + relu + fc3 -> logits
    head_kernel<<<BATCH / 16, 256>>>(h1, w2t, b2, w3, b3, (float*)d_out);
}

// round 5
// speedup vs baseline: 1.9837x; 1.1391x over previous
#include <cuda_runtime.h>
#include <cuda_bf16.h>
#include <cstdint>
#include <math.h>

#define NCARDS 10000
#define BATCH  16384

// ---------------- scratch (static device globals; no allocation) ----------------
__device__ __nv_bfloat16 g_embh[NCARDS * 256];   // emb hi
__device__ __nv_bfloat16 g_embl[NCARDS * 256];   // emb lo
__device__ __nv_bfloat16 g_iwh [2 * 768 * 256];  // in_w (my|op) hi
__device__ __nv_bfloat16 g_iwl [2 * 768 * 256];  // in_w (my|op) lo
__device__ float         g_P   [NCARDS * 1536];  // per-card projections
__device__ __nv_bfloat16 g_meanh[BATCH * 512];   // mean attn hi
__device__ __nv_bfloat16 g_meanl[BATCH * 512];   // mean attn lo
__device__ __nv_bfloat16 g_wch [256 * 512];      // combined weight hi
__device__ __nv_bfloat16 g_wcl [256 * 512];      // combined weight lo
__device__ float         g_bc  [256];            // combined bias
__device__ float         g_h1  [BATCH * 256];    // after w1 (LN in place)
__device__ float         g_w2t [256 * 64];       // w2 transposed

// ---------------- helpers ----------------
__device__ __forceinline__ uint32_t smem_u32(const void* p) {
    uint32_t a;
    asm("{ .reg .u64 t; cvta.to.shared.u64 t, %1; cvt.u32.u64 %0, t; }" : "=r"(a) : "l"(p));
    return a;
}
__device__ __forceinline__ void split_bf(float f, __nv_bfloat16& h, __nv_bfloat16& l) {
    h = __float2bfloat16_rn(f);
    l = __float2bfloat16_rn(f - __bfloat162float(h));
}

#define LDMX4(r, a) asm volatile("ldmatrix.sync.aligned.m8n8.x4.shared.b16 {%0,%1,%2,%3}, [%4];" \
    : "=r"((r)[0]), "=r"((r)[1]), "=r"((r)[2]), "=r"((r)[3]) : "r"(a))
#define LDMX2(r, a) asm volatile("ldmatrix.sync.aligned.m8n8.x2.shared.b16 {%0,%1}, [%2];" \
    : "=r"((r)[0]), "=r"((r)[1]) : "r"(a))

__device__ __forceinline__ void mma_bf16(float* d, const uint32_t* a, const uint32_t* b) {
    asm volatile("mma.sync.aligned.m16n8k16.row.col.f32.bf16.bf16.f32 "
        "{%0,%1,%2,%3}, {%4,%5,%6,%7}, {%8,%9}, {%0,%1,%2,%3};"
        : "+f"(d[0]), "+f"(d[1]), "+f"(d[2]), "+f"(d[3])
        : "r"(a[0]), "r"(a[1]), "r"(a[2]), "r"(a[3]), "r"(b[0]), "r"(b[1]));
}

// ================= split-bf16 tensor GEMM via mma.sync =================
// C[M,N] = (Ah+Al)[M,K] @ (Bh+Bl)[N,K]^T + bias[N]  (3-term product)
// tile 128x128, K-chunk 64, 256 threads (8 warps, 2x4), warp tile 64x32.
// smem: 4 tiles of 128 rows x 72 bf16 (pitch 144B, 16B-aligned, ldmatrix conflict-free)
#define TG_PITCH   144
#define TG_TILE    18432
#define TG_SMEM   (4 * TG_TILE)

__global__ void tgemm(const __nv_bfloat16* __restrict__ Ah, const __nv_bfloat16* __restrict__ Al,
                      const __nv_bfloat16* __restrict__ Bh, const __nv_bfloat16* __restrict__ Bl,
                      const float* __restrict__ bias, float* __restrict__ C,
                      int M, int K, int lda, int ldb, int ldc) {
    extern __shared__ char smem[];
    uint32_t sb = smem_u32(smem);
    int t = threadIdx.x, wid = t >> 5, lane = t & 31;
    int bm = blockIdx.y * 128, bn = blockIdx.x * 128;
    int warpM = (wid & 1) * 64, warpN = (wid >> 1) * 32;

    const uint32_t oAh = 0, oAl = TG_TILE, oBh = 2 * TG_TILE, oBl = 3 * TG_TILE;

    float acc[4][4][4];
#pragma unroll
    for (int i = 0; i < 4; i++)
#pragma unroll
        for (int j = 0; j < 4; j++)
#pragma unroll
            for (int q = 0; q < 4; q++) acc[i][j][q] = 0.f;

    int row = t >> 1, half = t & 1;                 // 128 rows x 2 halves
    bool aok = (bm + row) < M;
    const __nv_bfloat16* ArH = Ah + (size_t)(bm + row) * lda;
    const __nv_bfloat16* ArL = Al + (size_t)(bm + row) * lda;
    const __nv_bfloat16* BrH = Bh + (size_t)(bn + row) * ldb;
    const __nv_bfloat16* BrL = Bl + (size_t)(bn + row) * ldb;
    uint32_t dstA = row * TG_PITCH + half * 64;     // 32 bf16 = 64 bytes per half
    int nch = K >> 6;

    for (int c = 0; c < nch; c++) {
        int k0 = c * 64 + half * 32;
        __syncthreads();   // previous chunk's compute done before overwrite
        uint4 z = make_uint4(0, 0, 0, 0);
#pragma unroll
        for (int g = 0; g < 4; g++) {
            uint4 vh = aok ? *(const uint4*)&ArH[k0 + g * 8] : z;
            uint4 vl = aok ? *(const uint4*)&ArL[k0 + g * 8] : z;
            *(uint4*)(smem + oAh + dstA + g * 16) = vh;
            *(uint4*)(smem + oAl + dstA + g * 16) = vl;
            uint4 wh = *(const uint4*)&BrH[k0 + g * 8];
            uint4 wl = *(const uint4*)&BrL[k0 + g * 8];
            *(uint4*)(smem + oBh + dstA + g * 16) = wh;
            *(uint4*)(smem + oBl + dstA + g * 16) = wl;
        }
        __syncthreads();

#pragma unroll
        for (int ks = 0; ks < 4; ks++) {
            uint32_t bh[4][2], bl[4][2];
#pragma unroll
            for (int j = 0; j < 4; j++) {
                uint32_t ab = sb + oBh + (warpN + j * 8 + (lane & 7)) * TG_PITCH
                            + ks * 32 + ((lane >> 3) & 1) * 16;
                LDMX2(bh[j], ab);
                LDMX2(bl[j], ab + (oBl - oBh));
            }
#pragma unroll
            for (int i = 0; i < 4; i++) {
                uint32_t aa = sb + oAh + (warpM + i * 16 + (lane & 15)) * TG_PITCH
                            + ks * 32 + (lane >> 4) * 16;
                uint32_t ah[4], al[4];
                LDMX4(ah, aa);
                LDMX4(al, aa + (oAl - oAh));
#pragma unroll
                for (int j = 0; j < 4; j++) {
                    mma_bf16(acc[i][j], ah, bh[j]);
                    mma_bf16(acc[i][j], ah, bl[j]);
                    mma_bf16(acc[i][j], al, bh[j]);
                }
            }
        }
    }

    // epilogue: fragment -> gmem with bias
#pragma unroll
    for (int i = 0; i < 4; i++) {
        int r0 = bm + warpM + i * 16 + (lane >> 2);
#pragma unroll
        for (int j = 0; j < 4; j++) {
            int cN = bn + warpN + j * 8 + (lane & 3) * 2;
            float b0 = bias[cN], b1 = bias[cN + 1];
            if (r0 < M)
                *(float2*)&C[(size_t)r0 * ldc + cN] =
                    make_float2(acc[i][j][0] + b0, acc[i][j][1] + b1);
            if (r0 + 8 < M)
                *(float2*)&C[(size_t)(r0 + 8) * ldc + cN] =
                    make_float2(acc[i][j][2] + b0, acc[i][j][3] + b1);
        }
    }
}

// ---------------- K1: card embeddings (split-bf16 output) ----------------
__global__ void emb_kernel(const float* __restrict__ xr, const float* __restrict__ xi) {
    int idx = blockIdx.x * 256 + threadIdx.x;
    if (idx >= NCARDS * 128) return;
    int c = idx >> 7, d = idx & 127;
    float a = xr[idx], b = xi[idx];
    float amp = sqrtf(a * a + b * b + 1e-8f);
    float ph  = atan2f(b, a);
    __nv_bfloat16 h, l;
    split_bf(amp, h, l);
    g_embh[c * 256 + d] = h; g_embl[c * 256 + d] = l;
    split_bf(ph, h, l);
    g_embh[c * 256 + 128 + d] = h; g_embl[c * 256 + 128 + d] = l;
}

// ---------------- elementwise split ----------------
__global__ void split_kernel(const float* __restrict__ src, __nv_bfloat16* __restrict__ dh,
                             __nv_bfloat16* __restrict__ dl, int n) {
    int i = blockIdx.x * 256 + threadIdx.x;
    if (i >= n) return;
    __nv_bfloat16 h, l;
    split_bf(src[i], h, l);
    dh[i] = h; dl[i] = l;
}

// ---------------- combined weight build (parallel, smem-staged) ----------------
// wc[n][half*256+k] = sum_j w1[n][half*256+j] * W[j][k];  4 rows per block, 128 blocks
__global__ void build_wc_kernel(const float* __restrict__ w1, const float* __restrict__ wmy,
                                const float* __restrict__ wop) {
    __shared__ float sw1[4][256];
    int k = threadIdx.x;
    int half = blockIdx.y;
    int n0 = blockIdx.x * 4;
    const float* W = half ? wop : wmy;
#pragma unroll
    for (int q = 0; q < 4; q++) {
        int idx = threadIdx.x + q * 256;
        int r = idx >> 8, c = idx & 255;
        sw1[r][c] = w1[(size_t)(n0 + r) * 512 + half * 256 + c];
    }
    __syncthreads();
    float acc[4] = {0.f, 0.f, 0.f, 0.f};
    for (int j = 0; j < 256; j += 8) {
#pragma unroll
        for (int jj = 0; jj < 8; jj++) {
            float wv = W[(j + jj) * 256 + k];
#pragma unroll
            for (int i = 0; i < 4; i++) acc[i] += sw1[i][j + jj] * wv;
        }
    }
#pragma unroll
    for (int i = 0; i < 4; i++) {
        __nv_bfloat16 h, l;
        split_bf(acc[i], h, l);
        size_t o = (size_t)(n0 + i) * 512 + half * 256 + k;
        g_wch[o] = h; g_wcl[o] = l;
    }
}

__global__ void build_bc_kernel(const float* __restrict__ b1, const float* __restrict__ w1,
                                const float* __restrict__ bmy, const float* __restrict__ bop) {
    int n = threadIdx.x;
    float acc = b1[n];
    for (int j = 0; j < 256; j++) {
        acc += w1[(size_t)n * 512 + j]       * bmy[j];
        acc += w1[(size_t)n * 512 + 256 + j] * bop[j];
    }
    g_bc[n] = acc;
}

// ---------------- K3: per-batch dual cross-attention, mean-collapsed ----------------
#define RP 260
__global__ void attn_kernel(const int* __restrict__ my_decks, const int* __restrict__ op_decks,
                            const int* __restrict__ adj, const float* __restrict__ P) {
    __shared__ int   sMy[8], sOp[8];
    __shared__ float sMat[4][8][RP];
    __shared__ float sBias[8][8];
    __shared__ float sS[2][4][8][8];
    __shared__ float sW[2][4][8];

    int b = blockIdx.x, t = threadIdx.x;
    if (t < 8)        sMy[t]     = my_decks[b * 8 + t];
    else if (t < 16)  sOp[t - 8] = op_decks[b * 8 + (t - 8)];
    __syncthreads();

    if (t < 64) {
        int i = t >> 3, j = t & 7;
        sBias[i][j] = (adj[(size_t)sMy[i] * NCARDS + sOp[j]] > 0) ? 0.f : -10000.f;
    }

    const int offs[4] = {0, 768, 256, 1024};
#pragma unroll
    for (int it = 0; it < 8; it++) {
        int idx  = t + it * 256;
        int row  = idx >> 6;
        int c4   = idx & 63;
        int mat  = row >> 3, slot = row & 7;
        int card = (mat == 0 || mat == 3) ? sMy[slot] : sOp[slot];
        float4 v = *(const float4*)&P[(size_t)card * 1536 + offs[mat] + c4 * 4];
        ((float4*)&sMat[mat][slot][0])[c4] = v;
    }
    __syncthreads();

    {
        int s  = t >> 7;
        int h  = (t >> 5) & 3;
        int a  = (t >> 2) & 7;
        int b0 = (t & 3) * 2;
        const float* q  = &sMat[s][a][h * 64];
        const float* k0 = &sMat[2 + s][b0][h * 64];
        const float* k1 = &sMat[2 + s][b0 + 1][h * 64];
        float d0 = 0.f, d1 = 0.f;
#pragma unroll
        for (int d = 0; d < 64; d += 4) {
            float4 qv  = *(const float4*)&q[d];
            float4 kv0 = *(const float4*)&k0[d];
            float4 kv1 = *(const float4*)&k1[d];
            d0 += qv.x * kv0.x + qv.y * kv0.y + qv.z * kv0.z + qv.w * kv0.w;
            d1 += qv.x * kv1.x + qv.y * kv1.y + qv.z * kv1.z + qv.w * kv1.w;
        }
        float bi0 = (s == 0) ? sBias[a][b0]     : sBias[b0][a];
        float bi1 = (s == 0) ? sBias[a][b0 + 1] : sBias[b0 + 1][a];
        sS[s][h][a][b0]     = d0 * 0.125f + bi0;
        sS[s][h][a][b0 + 1] = d1 * 0.125f + bi1;
    }
    __syncthreads();

    if (t < 64) {
        int s = t >> 5, h = (t >> 3) & 3, a = t & 7;
        float* row = &sS[s][h][a][0];
        float m = row[0];
#pragma unroll
        for (int j = 1; j < 8; j++) m = fmaxf(m, row[j]);
        float p[8], sum = 0.f;
#pragma unroll
        for (int j = 0; j < 8; j++) { p[j] = __expf(row[j] - m); sum += p[j]; }
        float inv = 1.f / sum;
#pragma unroll
        for (int j = 0; j < 8; j++) row[j] = p[j] * inv;
    }
    __syncthreads();

    if (t < 64) {
        int s = t >> 5, h = (t >> 3) & 3, bb = t & 7;
        float w = 0.f;
#pragma unroll
        for (int a = 0; a < 8; a++) w += sS[s][h][a][bb];
        sW[s][h][bb] = w * 0.125f;
    }
    __syncthreads();

    {
        int s  = t >> 7;
        int d0 = (t & 127) * 2;
        int h  = d0 >> 6;
        int off = (s == 0) ? 512 : 1280;
        float w[8];
#pragma unroll
        for (int j = 0; j < 8; j++) w[j] = sW[s][h][j];
        float acc0 = 0.f, acc1 = 0.f;
#pragma unroll
        for (int j = 0; j < 8; j++) {
            int card = (s == 0) ? sOp[j] : sMy[j];
            float2 v = *(const float2*)&P[(size_t)card * 1536 + off + d0];
            acc0 += w[j] * v.x; acc1 += w[j] * v.y;
        }
        // write split-bf16 directly (feeds the h1 tensor GEMM)
        __nv_bfloat16 h0, l0, h1, l1;
        split_bf(acc0, h0, l0);
        split_bf(acc1, h1, l1);
        size_t o = (size_t)b * 512 + s * 256 + d0;
        *(__nv_bfloat162*)&g_meanh[o] = __nv_bfloat162(h0, h1);
        *(__nv_bfloat162*)&g_meanl[o] = __nv_bfloat162(l0, l1);
    }
}

// ---------------- K6: LayerNorm + ReLU ----------------
__global__ void ln_relu_kernel(float* __restrict__ h, const float* __restrict__ g,
                               const float* __restrict__ be) {
    int w = threadIdx.x >> 5, lane = threadIdx.x & 31;
    int row = blockIdx.x * 8 + w;
    float* rp = h + (size_t)row * 256;
    float4 v0 = *(float4*)&rp[lane * 8];
    float4 v1 = *(float4*)&rp[lane * 8 + 4];
    float vals[8] = {v0.x, v0.y, v0.z, v0.w, v1.x, v1.y, v1.z, v1.w};
    float s = 0.f, sq = 0.f;
#pragma unroll
    for (int q = 0; q < 8; q++) { s += vals[q]; sq += vals[q] * vals[q]; }
#pragma unroll
    for (int o = 16; o; o >>= 1) {
        s  += __shfl_xor_sync(0xffffffffu, s,  o);
        sq += __shfl_xor_sync(0xffffffffu, sq, o);
    }
    float mu   = s * (1.f / 256.f);
    float var  = sq * (1.f / 256.f) - mu * mu;
    float rstd = rsqrtf(var + 1e-5f);
#pragma unroll
    for (int q = 0; q < 8; q++) {
        int idx = lane * 8 + q;
        vals[q] = fmaxf(0.f, (vals[q] - mu) * rstd * g[idx] + be[idx]);
    }
    *(float4*)&rp[lane * 8]     = make_float4(vals[0], vals[1], vals[2], vals[3]);
    *(float4*)&rp[lane * 8 + 4] = make_float4(vals[4], vals[5], vals[6], vals[7]);
}

// ---------------- w2 transpose ----------------
__global__ void w2t_kernel(const float* __restrict__ w2) {
    int idx = blockIdx.x * 256 + threadIdx.x;
    int n = idx >> 8, k = idx & 255;
    g_w2t[k * 64 + n] = w2[idx];
}

// ---------------- K7/K8: fc2 + relu + fc3 ----------------
__global__ void head_kernel(const float* __restrict__ h, const float* __restrict__ w2t,
                            const float* __restrict__ b2, const float* __restrict__ w3,
                            const float* __restrict__ b3, float* __restrict__ out) {
    __shared__ float sH[4][256];
    __shared__ float sPart[4][2];
    int t = threadIdx.x;
    int rsub = t >> 6, n = t & 63, lane = t & 31;
    float b2n = b2[n], w3n = w3[n], b3v = b3[0];

    for (int it = 0; it < 4; it++) {
        __syncthreads();
#pragma unroll
        for (int q = 0; q < 4; q++) {
            int fi = t + q * 256;
            int rr = fi >> 8, cc = fi & 255;
            sH[rr][cc] = h[(size_t)(blockIdx.x * 16 + it * 4 + rr) * 256 + cc];
        }
        __syncthreads();
        float acc = 0.f;
#pragma unroll 8
        for (int k = 0; k < 256; k++) acc += sH[rsub][k] * w2t[k * 64 + n];
        float p = fmaxf(acc + b2n, 0.f) * w3n;
#pragma unroll
        for (int o = 16; o; o >>= 1) p += __shfl_xor_sync(0xffffffffu, p, o);
        if (lane == 0) sPart[rsub][(t >> 5) & 1] = p;
        __syncthreads();
        if (t < 4) out[blockIdx.x * 16 + it * 4 + t] = sPart[t][0] + sPart[t][1] + b3v;
    }
}

// ---------------- launch ----------------
extern "C" void kernel_launch(void* const* d_in, const int* in_sizes, int n_in,
                              void* d_out, int out_size) {
    (void)in_sizes; (void)n_in; (void)out_size;
    const float* x_real   = (const float*)d_in[0];
    const float* x_imag   = (const float*)d_in[1];
    const int*   my_decks = (const int*)  d_in[2];
    const int*   op_decks = (const int*)  d_in[3];
    const int*   adj      = (const int*)  d_in[4];
    const float* in_w_my  = (const float*)d_in[5];
    const float* in_b_my  = (const float*)d_in[6];
    const float* out_w_my = (const float*)d_in[7];
    const float* out_b_my = (const float*)d_in[8];
    const float* in_w_op  = (const float*)d_in[9];
    const float* in_b_op  = (const float*)d_in[10];
    const float* out_w_op = (const float*)d_in[11];
    const float* out_b_op = (const float*)d_in[12];
    const float* w1       = (const float*)d_in[13];
    const float* b1       = (const float*)d_in[14];
    const float* ln_g     = (const float*)d_in[15];
    const float* ln_b     = (const float*)d_in[16];
    const float* w2       = (const float*)d_in[17];
    const float* b2       = (const float*)d_in[18];
    const float* w3       = (const float*)d_in[19];
    const float* b3       = (const float*)d_in[20];

    __nv_bfloat16 *embh, *embl, *iwh, *iwl, *meanh, *meanl, *wch, *wcl;
    float *P, *bc, *h1, *w2t;
    cudaGetSymbolAddress((void**)&embh,  g_embh);
    cudaGetSymbolAddress((void**)&embl,  g_embl);
    cudaGetSymbolAddress((void**)&iwh,   g_iwh);
    cudaGetSymbolAddress((void**)&iwl,   g_iwl);
    cudaGetSymbolAddress((void**)&P,     g_P);
    cudaGetSymbolAddress((void**)&meanh, g_meanh);
    cudaGetSymbolAddress((void**)&meanl, g_meanl);
    cudaGetSymbolAddress((void**)&wch,   g_wch);
    cudaGetSymbolAddress((void**)&wcl,   g_wcl);
    cudaGetSymbolAddress((void**)&bc,    g_bc);
    cudaGetSymbolAddress((void**)&h1,    g_h1);
    cudaGetSymbolAddress((void**)&w2t,   g_w2t);

    cudaFuncSetAttribute(tgemm, cudaFuncAttributeMaxDynamicSharedMemorySize, TG_SMEM);

    // K1: embeddings (split-bf16)
    emb_kernel<<<(NCARDS * 128 + 255) / 256, 256>>>(x_real, x_imag);

    // split in_w matrices
    split_kernel<<<(768 * 256 + 255) / 256, 256>>>(in_w_my, iwh,             iwl,             768 * 256);
    split_kernel<<<(768 * 256 + 255) / 256, 256>>>(in_w_op, iwh + 768 * 256, iwl + 768 * 256, 768 * 256);

    // combined out-proj + w1 weight (split output), parallel version
    build_wc_kernel<<<dim3(64, 2), 256>>>(w1, out_w_my, out_w_op);
    build_bc_kernel<<<1, 256>>>(b1, w1, out_b_my, out_b_op);
    w2t_kernel<<<64, 256>>>(w2);

    // K2: per-card projection table P[10000][1536] (tensor mma.sync, split-bf16)
    dim3 gP(6, (NCARDS + 127) / 128);
    tgemm<<<gP, 256, TG_SMEM>>>(embh, embl, iwh,             iwl,             in_b_my, P,       NCARDS, 256, 256, 256, 1536);
    tgemm<<<gP, 256, TG_SMEM>>>(embh, embl, iwh + 768 * 256, iwl + 768 * 256, in_b_op, P + 768, NCARDS, 256, 256, 256, 1536);

    // K3: attention (mean-collapsed), writes split-bf16 mean
    attn_kernel<<<BATCH, 256>>>(my_decks, op_decks, adj, P);

    // K5': h1 = mean @ wc^T + bc (tensor mma.sync)
    dim3 gF(2, BATCH / 128);
    tgemm<<<gF, 256, TG_SMEM>>>(meanh, meanl, wch, wcl, bc, h1, BATCH, 512, 512, 512, 256);

    // K6: LayerNorm + ReLU (in place)
    ln_relu_kernel<<<BATCH / 8, 256>>>(h1, ln_g, ln_b);

    // K7/K8: fc2 + relu + fc3 -> logits
    head_kernel<<<BATCH / 16, 256>>>(h1, w2t, b2, w3, b3, (float*)d_out);
}